// round 2
// baseline (speedup 1.0000x reference)
#include <cuda_runtime.h>
#include <cstdint>

#define IMG_H 2048
#define IMG_W 4096
#define IMG_C 3

// Precomputed per-row (By . (5*D)) factors and per-col Bx spline weights.
__device__ float g_rowD[IMG_H][8];   // [h]: ry0,ry1,ry2,0, rx0,rx1,rx2,0
__device__ float g_bx[IMG_W][4];     // [w]: bx0,bx1,bx2,0

// Keys cubic (a=-0.5) tap weights for offsets -1..2 at fractional t in [0,1].
// w0 = outer(1+t) = -0.5*t*(1-t)^2
// w1 = inner(t)   = 1.5t^3 - 2.5t^2 + 1
// w2 = inner(1-t) = t*(0.5 + 2t - 1.5t^2)
// w3 = outer(2-t) = -0.5*t^2*(1-t)
__device__ __forceinline__ void cubic_w(float t, float& w0, float& w1, float& w2, float& w3) {
    float s = 1.0f - t;
    w0 = -0.5f * t * s * s;
    w1 = fmaf(fmaf(1.5f, t, -2.5f), t * t, 1.0f);
    w2 = t * fmaf(fmaf(-1.5f, t, 2.0f), t, 0.5f);
    w3 = -0.5f * t * t * s;
}

// 3 clamped-accumulated spline weights for output index i on an axis with
// n_out points and 3 control points (matches reference: u = (i*2)/(n_out-1),
// taps j0-1..j0+2 clamped to [0,2], weights accumulated).
__device__ __forceinline__ void spline3(int i, int n_out, float b[3]) {
    float u = ((float)i * 2.0f) / (float)(n_out - 1);
    float fj = floorf(u);
    int j0 = (int)fj;
    float t = u - fj;
    float w0, w1, w2, w3;
    cubic_w(t, w0, w1, w2, w3);
    float wv[4] = {w0, w1, w2, w3};
    b[0] = 0.0f; b[1] = 0.0f; b[2] = 0.0f;
#pragma unroll
    for (int a = 0; a < 4; a++) {
        int idx = j0 - 1 + a;
        idx = idx < 0 ? 0 : (idx > 2 ? 2 : idx);
        if (idx == 0) b[0] += wv[a];
        else if (idx == 1) b[1] += wv[a];
        else b[2] += wv[a];
    }
}

__global__ void prep_kernel(const float* __restrict__ disp) {
    int i = blockIdx.x * blockDim.x + threadIdx.x;
    if (i < IMG_H) {
        float by[3];
        spline3(i, IMG_H, by);
#pragma unroll
        for (int d = 0; d < 2; d++) {
#pragma unroll
            for (int x = 0; x < 3; x++) {
                float v = by[0] * (5.0f * __ldg(disp + d * 9 + 0 + x))
                        + by[1] * (5.0f * __ldg(disp + d * 9 + 3 + x))
                        + by[2] * (5.0f * __ldg(disp + d * 9 + 6 + x));
                g_rowD[i][d * 4 + x] = v;
            }
            g_rowD[i][d * 4 + 3] = 0.0f;
        }
    }
    if (i < IMG_W) {
        float bx[3];
        spline3(i, IMG_W, bx);
        g_bx[i][0] = bx[0];
        g_bx[i][1] = bx[1];
        g_bx[i][2] = bx[2];
        g_bx[i][3] = 0.0f;
    }
}

__global__ void __launch_bounds__(256)
warp_main(const float* __restrict__ img, float* __restrict__ out) {
    int x = blockIdx.x * 256 + threadIdx.x;
    int y = blockIdx.y;

    const float4* rdp = reinterpret_cast<const float4*>(g_rowD[y]);
    float4 ry = __ldg(rdp);        // warp-uniform
    float4 rx = __ldg(rdp + 1);    // warp-uniform
    float4 bx = __ldg(reinterpret_cast<const float4*>(g_bx[x]));

    float dispy = fmaf(ry.x, bx.x, fmaf(ry.y, bx.y, ry.z * bx.z));
    float dispx = fmaf(rx.x, bx.x, fmaf(rx.y, bx.y, rx.z * bx.z));

    float yy = (float)y + dispy;
    float xx = (float)x + dispx;
    float fy = floorf(yy), fx = floorf(xx);
    int iy0 = (int)fy, ix0 = (int)fx;
    float tyf = yy - fy, txf = xx - fx;

    float wy0, wy1, wy2, wy3, wx0, wx1, wx2, wx3;
    cubic_w(tyf, wy0, wy1, wy2, wy3);
    cubic_w(txf, wx0, wx1, wx2, wx3);
    float wyA[4] = {wy0, wy1, wy2, wy3};

    float accr = 0.0f, accg = 0.0f, accb = 0.0f;

    bool interior = (iy0 >= 1) && (iy0 <= IMG_H - 3) && (ix0 >= 1) && (ix0 <= IMG_W - 5);
    if (interior) {
        // Fast path: per tap-row, the 4 taps are 12 contiguous floats starting
        // at p0 (4-byte aligned). Row stride = W*3 floats (multiple of 4), so
        // the 16B-alignment phase is the same for all 4 rows.
        int p0 = ((iy0 - 1) * IMG_W + (ix0 - 1)) * IMG_C;
        bool s2 = (p0 & 2) != 0;
        bool s1 = (p0 & 1) != 0;
        const float4* q = reinterpret_cast<const float4*>(img + (p0 & ~3));
        const int row_q = (IMG_W * IMG_C) / 4;  // float4 stride per image row

#pragma unroll
        for (int a = 0; a < 4; a++) {
            float4 v0 = __ldg(q);
            float4 v1 = __ldg(q + 1);
            float4 v2 = __ldg(q + 2);
            float4 v3 = __ldg(q + 3);
            q += row_q;

            float r[16];
            r[0] = v0.x; r[1] = v0.y; r[2]  = v0.z; r[3]  = v0.w;
            r[4] = v1.x; r[5] = v1.y; r[6]  = v1.z; r[7]  = v1.w;
            r[8] = v2.x; r[9] = v2.y; r[10] = v2.z; r[11] = v2.w;
            r[12] = v3.x; r[13] = v3.y; r[14] = v3.z; r[15] = v3.w;

            // e[j] = r[j + (p0 & 3)] via two branchless select levels
            float u[13];
#pragma unroll
            for (int k = 0; k < 13; k++) u[k] = s2 ? r[k + 2] : r[k];
            float e[12];
#pragma unroll
            for (int j = 0; j < 12; j++) e[j] = s1 ? u[j + 1] : u[j];

            float sr = fmaf(wx3, e[9],  fmaf(wx2, e[6], fmaf(wx1, e[3], wx0 * e[0])));
            float sg = fmaf(wx3, e[10], fmaf(wx2, e[7], fmaf(wx1, e[4], wx0 * e[1])));
            float sb = fmaf(wx3, e[11], fmaf(wx2, e[8], fmaf(wx1, e[5], wx0 * e[2])));

            accr = fmaf(wyA[a], sr, accr);
            accg = fmaf(wyA[a], sg, accg);
            accb = fmaf(wyA[a], sb, accb);
        }
    } else {
        // Border slow path: clamped scalar taps (exactly the reference math).
        float wxA[4] = {wx0, wx1, wx2, wx3};
#pragma unroll
        for (int a = 0; a < 4; a++) {
            int tyc = iy0 - 1 + a;
            tyc = min(max(tyc, 0), IMG_H - 1);
            int rowb = tyc * IMG_W * IMG_C;
#pragma unroll
            for (int b = 0; b < 4; b++) {
                int txc = ix0 - 1 + b;
                txc = min(max(txc, 0), IMG_W - 1);
                int p = rowb + txc * IMG_C;
                float w = wyA[a] * wxA[b];
                accr = fmaf(w, __ldg(img + p),     accr);
                accg = fmaf(w, __ldg(img + p + 1), accg);
                accb = fmaf(w, __ldg(img + p + 2), accb);
            }
        }
    }

    int o = (y * IMG_W + x) * IMG_C;
    out[o]     = accr;
    out[o + 1] = accg;
    out[o + 2] = accb;
}

extern "C" void kernel_launch(void* const* d_in, const int* in_sizes, int n_in,
                              void* d_out, int out_size) {
    const float* img  = (const float*)d_in[0];
    const float* disp = (const float*)d_in[1];
    if (n_in >= 2 && in_sizes[0] == 18) {  // defensive: swap if order differs
        img  = (const float*)d_in[1];
        disp = (const float*)d_in[0];
    }

    prep_kernel<<<4, 1024>>>(disp);

    dim3 grid(IMG_W / 256, IMG_H);
    warp_main<<<grid, 256>>>(img, (float*)d_out);
}